// round 8
// baseline (speedup 1.0000x reference)
#include <cuda_runtime.h>
#include <math.h>

#define NCTA   128
#define NTHR   512
#define NWARP  16
#define TSTEPS 1000
#define BB     32
#define NN0    256
#define NN1    512
#define GG     4
#define NSPLIT 16
#define NBARS  1000ULL            // 1 (post phase-A) + 999 inter-step  — EXACT
#define BARM   (NBARS * (unsigned long long)NCTA)

typedef unsigned long long u64;

// Scratch: full layer-0 firing-rate trajectory, [t][n][b] (128B rows).
__device__ float g_s0traj[TSTEPS * NN0 * BB];          // 32 MB
// Layer-1 recurrent exchange (ping-pong) + monotonic barrier counter.
__device__ float g_spbuf[2][NN1 * BB];
__device__ unsigned long long g_arrive;

// ---- f32x2 helpers ----
__device__ __forceinline__ u64 pk2(float a, float b) {
    u64 r; asm("mov.b64 %0, {%1,%2};" : "=l"(r) : "f"(a), "f"(b)); return r;
}
__device__ __forceinline__ u64 ffma2(u64 a, u64 b, u64 c) {
    u64 d; asm("fma.rn.f32x2 %0, %1, %2, %3;" : "=l"(d) : "l"(a), "l"(b), "l"(c)); return d;
}
__device__ __forceinline__ u64 add2(u64 a, u64 b) {
    u64 d; asm("add.rn.f32x2 %0, %1, %2;" : "=l"(d) : "l"(a), "l"(b)); return d;
}
__device__ __forceinline__ void upk2(u64 v, float& a, float& b) {
    asm("mov.b64 {%0,%1}, %2;" : "=f"(a), "=f"(b) : "l"(v));
}
__device__ __forceinline__ u64 shfl_xor_u64(u64 v, int m) {
    unsigned lo = (unsigned)v, hi = (unsigned)(v >> 32);
    lo = __shfl_xor_sync(0xffffffffu, lo, m);
    hi = __shfl_xor_sync(0xffffffffu, hi, m);
    return ((u64)hi << 32) | lo;
}

__global__ void __launch_bounds__(NTHR, 1)
rsnn_kernel(const float* __restrict__ inp,
            const float* __restrict__ W1,
            const float* __restrict__ Wr,
            float* __restrict__ out)
{
    __shared__ float wp1[NN0 * GG];               // 4 KB prepacked [n][g]
    __shared__ float wpr[NN1 * GG];               // 8 KB prepacked [n][g]
    __shared__ float psum1[NSPLIT * GG * BB];     // 8 KB (lives ACROSS the barrier)
    __shared__ float psum2[NSPLIT * GG * BB];     // 8 KB
    __shared__ float sta[BB * GG];                // staged spa [b][g]
    __shared__ float stb[BB * GG];                // staged spb [b][g]
    __shared__ unsigned long long sh_base;

    const int tid   = threadIdx.x;
    const int cta   = blockIdx.x;
    const int ws    = tid >> 5;
    const int lane  = tid & 31;
    const int ng    = lane >> 3;      // 0..3 : n sub-slice within warp
    const int bg    = lane & 7;       // 0..7 : batch group (4 batches)
    const int mbase = cta * GG;

    // ---- GLIF constants ----
    const float CID = 0.95f;
    const float CIA = 0.05f;
    const float CVD = 0.99f;
    const float CVA = (float)(0.05 * (1.0 / 5.0) * (1.0 / 9.43));
    const float TH  = (float)(10.0 * 1.0986122886681098);
    const float AD0 = (float)(1.0 - 0.05 * 0.003);
    const float AD1 = (float)(1.0 - 0.05 * 0.1);
    const float AA0 = (float)(-9.18 * 0.05);
    const float AA1 = (float)(-198.94 * 0.05);

    // ---- one-time weight prepack: wp[n*4+g] = W[mbase+g][n] ----
    for (int i = tid; i < NN0 * GG; i += NTHR)
        wp1[i] = W1[(mbase + (i & 3)) * NN0 + (i >> 2)];
    for (int i = tid; i < NN1 * GG; i += NTHR)
        wpr[i] = Wr[(mbase + (i & 3)) * NN1 + (i >> 2)];

    // ---- launch-consistent barrier base ----
    if (tid == 0) {
        unsigned long long g = *(volatile unsigned long long*)&g_arrive;
        sh_base = (g / BARM) * BARM;
    }

    // ---- zero psum1 (h1 for t=0 is 0: delay buffer starts empty) ----
    for (int i = tid; i < NSPLIT * GG * BB; i += NTHR) psum1[i] = 0.0f;

    // ---- zero parity-1 spb buffer (initial delayed recurrent state) ----
    for (int i = tid; i < (NN1 * BB) / NCTA; i += NTHR)
        g_spbuf[1][cta * ((NN1 * BB) / NCTA) + i] = 0.0f;

    // ================= PHASE A: full layer-0 trajectory =================
    // 8192 independent GLIF chains; thread -> (n = 2*cta + tid/32, b = lane),
    // so s0traj stores (stride 32 in n*32+b) are fully coalesced per warp.
    // Software-pipelined: inp[t+1] load overlaps the dependent GLIF chain.
    if (tid < 64) {
        const int id = cta * 64 + tid;
        const int n  = id >> 5;
        const int b  = id & 31;
        float I0 = 0.f, V0 = 0.f, A00 = 0.f, A01 = 0.f;
        const float* ip = inp + b * NN0 + n;
        float*       op = g_s0traj + n * BB + b;
        float x = __ldg(ip);                       // prime
        for (int t = 0; t < TSTEPS; ++t) {
            float xn = (t + 1 < TSTEPS) ? __ldg(ip + (t + 1) * (BB * NN0)) : 0.0f;
            I0 = I0 * CID + CIA * x;
            V0 = V0 * CVD + CVA * (I0 + A00 + A01);
            float s = 20.0f / (1.0f + __expf((TH - V0) * 0.1f));
            A00 = A00 * AD0 + AA0 * s;
            A01 = A01 * AD1 + AA1 * s;
            op[t * (NN0 * BB)] = s;
            x = xn;
        }
    }

    // ---- barrier 0 (arrival #1): s0traj + spb zeroing globally visible ----
    __syncthreads();
    const unsigned long long base = sh_base;
    if (tid == 0) {
        __threadfence();
        atomicAdd(&g_arrive, 1ULL);
        while (*(volatile unsigned long long*)&g_arrive < base + NCTA) { }
        __threadfence();
    }
    __syncthreads();

    // ---- recurrent layer-1 state (reducer threads, tid < 128) ----
    float V1 = 0.f, I1 = 0.f, A10 = 0.f, A11 = 0.f;
    const int rg = tid >> 5;          // g
    const int rb = tid & 31;          // b

    const int nb1 = ws * (NN0 / NWARP);   // 16-wide n slice (GEMM1, in window)
    const int nb2 = ws * (NN1 / NWARP);   // 32-wide n slice (GEMM2, critical)

    for (int t = 0; t < TSTEPS; ++t) {
        const float* __restrict__ spr = g_spbuf[(t & 1) ^ 1];

        // ====== CRITICAL PATH: recurrent GEMM2 on freshly exchanged spb ======
        u64 acc2[8];
#pragma unroll
        for (int i = 0; i < 8; ++i) acc2[i] = 0ULL;
#pragma unroll
        for (int k = 0; k < 8; ++k) {
            const int n = nb2 + k * 4 + ng;
            float4 x4 = __ldcg((const float4*)(spr + n * BB + bg * 4));
            float4 w4 = *(const float4*)(wpr + n * 4);
            u64 x01 = pk2(x4.x, x4.y), x23 = pk2(x4.z, x4.w);
            u64 w0 = pk2(w4.x, w4.x), w1 = pk2(w4.y, w4.y);
            u64 w2 = pk2(w4.z, w4.z), w3 = pk2(w4.w, w4.w);
            acc2[0] = ffma2(w0, x01, acc2[0]); acc2[1] = ffma2(w0, x23, acc2[1]);
            acc2[2] = ffma2(w1, x01, acc2[2]); acc2[3] = ffma2(w1, x23, acc2[3]);
            acc2[4] = ffma2(w2, x01, acc2[4]); acc2[5] = ffma2(w2, x23, acc2[5]);
            acc2[6] = ffma2(w3, x01, acc2[6]); acc2[7] = ffma2(w3, x23, acc2[7]);
        }
#pragma unroll
        for (int i = 0; i < 8; ++i) {
            acc2[i] = add2(acc2[i], shfl_xor_u64(acc2[i], 8));
            acc2[i] = add2(acc2[i], shfl_xor_u64(acc2[i], 16));
        }
        if (ng == 0) {
            const int sbase = ws * (GG * BB) + bg * 4;
#pragma unroll
            for (int g = 0; g < GG; ++g) {
                float4 v2;
                upk2(acc2[g * 2], v2.x, v2.y); upk2(acc2[g * 2 + 1], v2.z, v2.w);
                *(float4*)&psum2[sbase + g * BB] = v2;
            }
        }
        __syncthreads();

        if (tid < 128) {
            // h1 from psum1 (computed last step's wait window), h2 from psum2
            float h1a = 0.f, h1b = 0.f, h2a = 0.f, h2b = 0.f;
#pragma unroll
            for (int s = 0; s < NSPLIT; s += 2) {
                h1a += psum1[s * (GG * BB) + rg * BB + rb];
                h1b += psum1[(s + 1) * (GG * BB) + rg * BB + rb];
                h2a += psum2[s * (GG * BB) + rg * BB + rb];
                h2b += psum2[(s + 1) * (GG * BB) + rg * BB + rb];
            }
            const float h1 = h1a + h1b, h2 = h2a + h2b;

            // call A (feedforward) -> sp_a
            I1 = I1 * CID + CIA * h1;
            V1 = V1 * CVD + CVA * (I1 + A10 + A11);
            float spa = 20.0f / (1.0f + __expf((TH - V1) * 0.1f));
            A10 = A10 * AD0 + AA0 * spa;
            A11 = A11 * AD1 + AA1 * spa;
            // call B (recurrent) -> sp_b
            I1 = I1 * CID + CIA * h2;
            V1 = V1 * CVD + CVA * (I1 + A10 + A11);
            float spb = 20.0f / (1.0f + __expf((TH - V1) * 0.1f));
            A10 = A10 * AD0 + AA0 * spb;
            A11 = A11 * AD1 + AA1 * spb;

            g_spbuf[t & 1][(mbase + rg) * BB + rb] = spb;   // exchange (critical)
            sta[rb * GG + rg] = spa;
            stb[rb * GG + rg] = spb;
        }

        // ================= split-phase grid barrier =================
        __syncthreads();                      // exchange + staging + psum1 reads done
        if (tid == 0 && t + 1 < TSTEPS) {     // ARRIVE early (none on final step:
            __threadfence();                  //  nobody waits on it, and arrival
            atomicAdd(&g_arrive, 1ULL);       //  count must equal NBARS exactly)
        }

        // ---- wait-window work (no cross-CTA consumer this step) ----
        if (ws == 0) {
            *(float4*)&out[(2 * t) * (BB * NN1) + lane * NN1 + mbase] =
                *(const float4*)&sta[lane * GG];
        } else if (ws == 1) {
            *(float4*)&out[(2 * t + 1) * (BB * NN1) + lane * NN1 + mbase] =
                *(const float4*)&stb[lane * GG];
        }
        if (t + 1 < TSTEPS) {
            // GEMM1 for step t+1: h1(t+1) = W1 * S0(t), static s0traj data.
            const float* __restrict__ s0r = g_s0traj + t * (NN0 * BB);
            u64 acc1[8];
#pragma unroll
            for (int i = 0; i < 8; ++i) acc1[i] = 0ULL;
#pragma unroll
            for (int k = 0; k < 4; ++k) {
                const int n = nb1 + k * 4 + ng;
                float4 x4 = __ldg((const float4*)(s0r + n * BB + bg * 4));
                float4 w4 = *(const float4*)(wp1 + n * 4);
                u64 x01 = pk2(x4.x, x4.y), x23 = pk2(x4.z, x4.w);
                u64 w0 = pk2(w4.x, w4.x), w1 = pk2(w4.y, w4.y);
                u64 w2 = pk2(w4.z, w4.z), w3 = pk2(w4.w, w4.w);
                acc1[0] = ffma2(w0, x01, acc1[0]); acc1[1] = ffma2(w0, x23, acc1[1]);
                acc1[2] = ffma2(w1, x01, acc1[2]); acc1[3] = ffma2(w1, x23, acc1[3]);
                acc1[4] = ffma2(w2, x01, acc1[4]); acc1[5] = ffma2(w2, x23, acc1[5]);
                acc1[6] = ffma2(w3, x01, acc1[6]); acc1[7] = ffma2(w3, x23, acc1[7]);
            }
#pragma unroll
            for (int i = 0; i < 8; ++i) {
                acc1[i] = add2(acc1[i], shfl_xor_u64(acc1[i], 8));
                acc1[i] = add2(acc1[i], shfl_xor_u64(acc1[i], 16));
            }
            if (ng == 0) {
                const int sbase = ws * (GG * BB) + bg * 4;
#pragma unroll
                for (int g = 0; g < GG; ++g) {
                    float4 v1;
                    upk2(acc1[g * 2], v1.x, v1.y); upk2(acc1[g * 2 + 1], v1.z, v1.w);
                    *(float4*)&psum1[sbase + g * BB] = v1;
                }
            }

            if (tid == 0) {                   // WAIT
                const unsigned long long tgt =
                    base + (unsigned long long)(t + 2) * NCTA;
                while (*(volatile unsigned long long*)&g_arrive < tgt) { }
                __threadfence();
            }
            __syncthreads();                  // release + orders psum1 for next step
        }
    }
}

extern "C" void kernel_launch(void* const* d_in, const int* in_sizes, int n_in,
                              void* d_out, int out_size) {
    const float* inp = (const float*)d_in[0];
    const float* W1  = (const float*)d_in[1];
    const float* Wr  = (const float*)d_in[2];
    float* out       = (float*)d_out;
    rsnn_kernel<<<NCTA, NTHR>>>(inp, W1, Wr, out);
}